// round 11
// baseline (speedup 1.0000x reference)
#include <cuda_runtime.h>

#define NCLS 128
#define EDIM 512
#define SHOT 1024
#define NROWS (NCLS * SHOT)
#define EMBD 64
#define VDIM 32
#define TASKD 64
#define KCL 32

#define NMT (NROWS / 128)    // 1024 M-tiles of 128 rows (class-major: 8 tiles/class)
#define TK 64                // 64 s8 per k-chunk (64B rows, same layout as 32xfp16)
#define NK (EDIM / TK)       // 8 k-chunks
#define STAGE 16384          // A 8K | B 8K

// quantization scales
#define SX 21.0f             // x:  |x| < 6.05 -> no clip at ~1.5e-9/elem
#define SW 2873.0f           // w:  |w| < 1/sqrt(512) exactly -> |q| < 127
#define ST 31.0f             // t = relu(h1): |t| < 4.1 w/ huge margin
#define INV1 (1.0f / (SX * SW))
#define INV2 (1.0f / (ST * SW))

typedef unsigned int u32;
typedef unsigned short u16;

// ------------------------- device scratch ----------------------------------
__device__ __align__(128) signed char g_X[(size_t)NROWS * EDIM];  // s8(x*SX), class-major
__device__ __align__(128) signed char g_H[(size_t)NROWS * EDIM];  // s8(relu(h1)*ST)
__device__ __align__(128) signed char g_W[2 * EDIM * EDIM];       // [mat][n][k] s8(w*SW)
__device__ float g_psum[NMT * EDIM];
__device__ float g_psq [NMT * EDIM];
__device__ float g_mnorm[NCLS * EDIM];
__device__ float g_v[NCLS * VDIM];
__device__ float g_simpart[NCLS];

// ------------------------- helpers -----------------------------------------
__device__ __forceinline__ u32 smem_u32(const void* p) {
    u32 a;
    asm("{ .reg .u64 t; cvta.to.shared.u64 t, %1; cvt.u32.u64 %0, t; }" : "=r"(a) : "l"(p));
    return a;
}
__device__ __forceinline__ void cpa16(u32 dst, const void* src) {
    asm volatile("cp.async.cg.shared.global [%0], [%1], 16;" :: "r"(dst), "l"(src) : "memory");
}
#define CP_COMMIT() asm volatile("cp.async.commit_group;" ::: "memory")
#define CP_WAIT(n)  asm volatile("cp.async.wait_group %0;" :: "n"(n) : "memory")

__device__ __forceinline__ u32 swz64(u32 off) { return off ^ ((off >> 3) & 0x30); }

__device__ __forceinline__ void ldm4(u32* r, u32 addr) {
    asm volatile("ldmatrix.sync.aligned.m8n8.x4.shared.b16 {%0,%1,%2,%3}, [%4];"
                 : "=r"(r[0]), "=r"(r[1]), "=r"(r[2]), "=r"(r[3]) : "r"(addr));
}
__device__ __forceinline__ void mma_s8(int* d, const u32* a, const u32* b) {
    asm volatile(
        "mma.sync.aligned.m16n8k32.row.col.s32.s8.s8.s32 "
        "{%0,%1,%2,%3}, {%4,%5,%6,%7}, {%8,%9}, {%0,%1,%2,%3};"
        : "+r"(d[0]), "+r"(d[1]), "+r"(d[2]), "+r"(d[3])
        : "r"(a[0]), "r"(a[1]), "r"(a[2]), "r"(a[3]), "r"(b[0]), "r"(b[1]));
}
__device__ __forceinline__ int q8(float v, float s) {
    int q = __float2int_rn(v * s);
    return max(-127, min(127, q));
}

// ---------------------------------------------------------------------------
// splitx: x f32 [131072,512] row i=(shot*128+class) -> class-major s8
// ---------------------------------------------------------------------------
__global__ __launch_bounds__(256) void splitx_kernel(const float* __restrict__ x)
{
    size_t g = (size_t)blockIdx.x * 256 + threadIdx.x;   // over NROWS*128 float4s
    int i = (int)(g >> 7), e4 = (int)(g & 127);
    float4 v = ((const float4*)(x + (size_t)i * EDIM))[e4];
    int p = (i & 127) * SHOT + (i >> 7);
    u32 q = (u32)(q8(v.x, SX) & 0xFF) | ((u32)(q8(v.y, SX) & 0xFF) << 8) |
            ((u32)(q8(v.z, SX) & 0xFF) << 16) | ((u32)(q8(v.w, SX) & 0xFF) << 24);
    ((u32*)(g_X + (size_t)p * EDIM))[e4] = q;
}

// ---------------------------------------------------------------------------
// splitw: W [512 k][512 n] f32 -> transposed [n][k] s8
// ---------------------------------------------------------------------------
__global__ __launch_bounds__(256) void splitw_kernel(const float* __restrict__ W0,
                                                     const float* __restrict__ W1)
{
    int idx = blockIdx.x * 256 + threadIdx.x;            // 0..262143
    const float* W = blockIdx.y ? W1 : W0;
    size_t base = (size_t)blockIdx.y * EDIM * EDIM;
    int k = idx >> 9, n = idx & 511;
    g_W[base + (size_t)n * EDIM + k] = (signed char)q8(W[idx], SW);
}

// ---------------------------------------------------------------------------
// GEMM via mma.sync m16n8k32 s8 (s32 exact accumulation).
// CTA tile 128(M) x 128(N), K chunks of 64 s8 (64B rows -> same smem layout,
// swizzle, and ldmatrix addressing as the fp16 version), 3-stage cp.async
// pipeline (48KB) -> 2 CTAs/SM. 8 warps, warp grid 2(M) x 4(N), tile 64x32.
// PHASE 0: h1 = acc*INV1 + b0; H = s8(relu(h1)*ST)
// PHASE 1: h  = acc*INV2 + b1 -> per-tile column sums of h, h^2
// ---------------------------------------------------------------------------
template <int PHASE>
__global__ __launch_bounds__(256, 2) void gemm_kernel(const float* __restrict__ bias)
{
    const int nh  = blockIdx.x;      // N tile (0..3)
    const int mt  = blockIdx.y;      // M tile (0..1023)
    const int tid = threadIdx.x;
    const int L   = tid & 31;
    const int warp = tid >> 5;
    const int warpM = warp & 1;      // 0..1
    const int warpN = warp >> 1;     // 0..3

    extern __shared__ __align__(1024) char sm[];
    const u32 smb = smem_u32(sm);

    const signed char* A = (PHASE ? g_H : g_X);
    const signed char* B = g_W + (size_t)PHASE * EDIM * EDIM;

    int c[4][4][4];
#pragma unroll
    for (int mf = 0; mf < 4; mf++)
#pragma unroll
        for (int nf = 0; nf < 4; nf++)
#pragma unroll
            for (int r = 0; r < 4; r++) c[mf][nf][r] = 0;

    // ldmatrix lane address components (64B rows; bytes)
    const int rA0 = warpM * 64 + (L & 7) + 8 * ((L >> 3) & 1);
    const u32 kA  = (u32)(L >> 4) * 16;
    const int rB0 = warpN * 32 + (L & 7) + 8 * (L >> 4);
    const u32 kB  = (u32)((L >> 3) & 1) * 16;

    auto load_stage = [&](int kc, int st) {
        const u32 base = smb + (u32)st * STAGE;
#pragma unroll
        for (int it = 0; it < 2; it++) {
            int t = tid + it * 256;          // 0..511
            int row = t >> 2, seg = t & 3;
            u32 off = swz64((u32)(row * 64 + seg * 16));
            cpa16(base + off,        A + (size_t)(mt * 128 + row) * EDIM + kc * TK + seg * 16);
            cpa16(base + 8192 + off, B + (size_t)(nh * 128 + row) * EDIM + kc * TK + seg * 16);
        }
        CP_COMMIT();
    };

    load_stage(0, 0);
    load_stage(1, 1);
    int st = 0;
    for (int kc = 0; kc < NK; kc++) {
        if (kc < NK - 2)      { load_stage(kc + 2, (st + 2) % 3); CP_WAIT(2); }
        else if (kc == NK - 2) CP_WAIT(1);
        else                   CP_WAIT(0);
        __syncthreads();

        const u32 base = smb + (u32)st * STAGE;
        const u32 aB = base, bB = base + 8192;
#pragma unroll
        for (int kk = 0; kk < 2; kk++) {     // two k32 halves of the 64-k chunk
            u32 bfr[2][4];
#pragma unroll
            for (int nf2 = 0; nf2 < 2; nf2++) {
                u32 off = swz64((u32)((rB0 + nf2 * 16) * 64) + (u32)(kk * 32) + kB);
                ldm4(bfr[nf2], bB + off);
            }
#pragma unroll
            for (int mf = 0; mf < 4; mf++) {
                u32 a[4];
                u32 off = swz64((u32)((rA0 + mf * 16) * 64) + (u32)(kk * 32) + kA);
                ldm4(a, aB + off);
#pragma unroll
                for (int nf = 0; nf < 4; nf++)
                    mma_s8(c[mf][nf], a, &bfr[nf >> 1][(nf & 1) * 2]);
            }
        }
        __syncthreads();
        st = (st + 1) % 3;
    }

    // ------------------------------ epilogue -------------------------------
    const int colT = nh * 128 + warpN * 32 + 2 * (L & 3);   // global col of par 0
    float bv[4][2];
#pragma unroll
    for (int nf = 0; nf < 4; nf++) {
        bv[nf][0] = bias[colT + nf * 8];
        bv[nf][1] = bias[colT + nf * 8 + 1];
    }

    if (PHASE == 0) {
#pragma unroll
        for (int mf = 0; mf < 4; mf++) {
            const int r0 = mt * 128 + warpM * 64 + mf * 16 + (L >> 2);
            const int r1 = r0 + 8;
#pragma unroll
            for (int nf = 0; nf < 4; nf++) {
                const int col = colT + nf * 8;
                float h0 = fmaxf((float)c[mf][nf][0] * INV1 + bv[nf][0], 0.0f);
                float h1 = fmaxf((float)c[mf][nf][1] * INV1 + bv[nf][1], 0.0f);
                float h2 = fmaxf((float)c[mf][nf][2] * INV1 + bv[nf][0], 0.0f);
                float h3 = fmaxf((float)c[mf][nf][3] * INV1 + bv[nf][1], 0.0f);
                u16 p0 = (u16)((q8(h0, ST) & 0xFF) | ((q8(h1, ST) & 0xFF) << 8));
                u16 p1 = (u16)((q8(h2, ST) & 0xFF) | ((q8(h3, ST) & 0xFF) << 8));
                *(u16*)(g_H + (size_t)r0 * EDIM + col) = p0;
                *(u16*)(g_H + (size_t)r1 * EDIM + col) = p1;
            }
        }
    } else {
        float s[4][2], q[4][2];
#pragma unroll
        for (int nf = 0; nf < 4; nf++)
#pragma unroll
            for (int par = 0; par < 2; par++) { s[nf][par] = 0.0f; q[nf][par] = 0.0f; }
#pragma unroll
        for (int mf = 0; mf < 4; mf++)
#pragma unroll
            for (int nf = 0; nf < 4; nf++) {
                float h0 = (float)c[mf][nf][0] * INV2 + bv[nf][0];
                float h1 = (float)c[mf][nf][1] * INV2 + bv[nf][1];
                float h2 = (float)c[mf][nf][2] * INV2 + bv[nf][0];
                float h3 = (float)c[mf][nf][3] * INV2 + bv[nf][1];
                s[nf][0] += h0 + h2; q[nf][0] += h0 * h0 + h2 * h2;
                s[nf][1] += h1 + h3; q[nf][1] += h1 * h1 + h3 * h3;
            }
#pragma unroll
        for (int m = 4; m <= 16; m <<= 1)
#pragma unroll
            for (int nf = 0; nf < 4; nf++)
#pragma unroll
                for (int par = 0; par < 2; par++) {
                    s[nf][par] += __shfl_xor_sync(0xFFFFFFFFu, s[nf][par], m);
                    q[nf][par] += __shfl_xor_sync(0xFFFFFFFFu, q[nf][par], m);
                }
        float* reds = (float*)sm;          // [2][128]
        float* redq = reds + 256;
        if (L < 4) {
#pragma unroll
            for (int nf = 0; nf < 4; nf++)
#pragma unroll
                for (int par = 0; par < 2; par++) {
                    int col = warpN * 32 + nf * 8 + 2 * L + par;
                    reds[warpM * 128 + col] = s[nf][par];
                    redq[warpM * 128 + col] = q[nf][par];
                }
        }
        __syncthreads();
        if (tid < 128) {
            g_psum[(size_t)mt * EDIM + nh * 128 + tid] = reds[tid] + reds[128 + tid];
            g_psq [(size_t)mt * EDIM + nh * 128 + tid] = redq[tid] + redq[128 + tid];
        }
    }
}

// ---------------------------------------------------------------------------
// k2a: per class — reduce 8 tile partials, mean/var, mnorm, stats MLP -> v
// ---------------------------------------------------------------------------
__global__ __launch_bounds__(64)
void k2a_kernel(const float* __restrict__ Ws,  const float* __restrict__ bs,
                const float* __restrict__ Wv0, const float* __restrict__ bv0,
                const float* __restrict__ Wv1, const float* __restrict__ bv1)
{
    const int c = blockIdx.x;
    const int t = threadIdx.x;
    __shared__ float mean_s[EDIM], var_s[EDIM], red[64], sv[EMBD], u[VDIM];

    for (int e = t; e < EDIM; e += 64) {
        float ss = 0.0f, sq = 0.0f;
#pragma unroll
        for (int sub = 0; sub < 8; sub++) {
            ss += g_psum[(size_t)(c * 8 + sub) * EDIM + e];
            sq += g_psq [(size_t)(c * 8 + sub) * EDIM + e];
        }
        float m = ss * (1.0f / 1024.0f);
        mean_s[e] = m;
        var_s[e]  = (sq - 1024.0f * m * m) * (1.0f / 1023.0f);
    }
    __syncthreads();

    float ps = 0.0f;
    for (int e = t; e < EDIM; e += 64) { float m = mean_s[e]; ps += m * m; }
    red[t] = ps; __syncthreads();
    for (int off = 32; off > 0; off >>= 1) {
        if (t < off) red[t] += red[t + off];
        __syncthreads();
    }
    float inv = 1.0f / fmaxf(sqrtf(red[0]), 1e-7f);
    for (int e = t; e < EDIM; e += 64) g_mnorm[c * EDIM + e] = mean_s[e] * inv;

    float acc = bs[t] + Ws[1024 * EMBD + t];   // Nc == 1
    for (int i = 0; i < EDIM; i++) acc += var_s[i] * Ws[i * EMBD + t];
    for (int i = 0; i < EDIM; i++) acc += mean_s[i] * Ws[(EDIM + i) * EMBD + t];
    sv[t] = fmaxf(acc, 0.0f);
    __syncthreads();

    if (t < VDIM) {
        float a = bv0[t];
        for (int i = 0; i < EMBD; i++) a += sv[i] * Wv0[i * VDIM + t];
        u[t] = fmaxf(a, 0.0f);
    }
    __syncthreads();
    if (t < VDIM) {
        float a = bv1[t];
        for (int i = 0; i < VDIM; i++) a += u[i] * Wv1[i * VDIM + t];
        g_v[c * VDIM + t] = a;
    }
}

// ---------------------------------------------------------------------------
__global__ __launch_bounds__(256) void k2b_kernel()
{
    const int i = blockIdx.x;
    const int t = threadIdx.x;
    __shared__ float mi[EDIM];
    __shared__ float red[256];
    for (int e = t; e < EDIM; e += 256) mi[e] = g_mnorm[i * EDIM + e];
    __syncthreads();
    float acc = 0.0f;
    for (int e = t; e < EDIM; e += 256) {
        float ws = 0.0f;
        for (int j = i + 1; j < NCLS; j++) ws += (float)(j - i) * g_mnorm[j * EDIM + e];
        acc += ws * mi[e];
    }
    red[t] = acc; __syncthreads();
    for (int off = 128; off > 0; off >>= 1) {
        if (t < off) red[t] += red[t + off];
        __syncthreads();
    }
    if (t == 0) g_simpart[i] = red[0];
}

// ---------------------------------------------------------------------------
__global__ __launch_bounds__(64)
void k3_kernel(const float* __restrict__ W2, const float* __restrict__ b2,
               const float* __restrict__ memv, float* __restrict__ out)
{
    const int t = threadIdx.x;
    __shared__ float vv[66], task[TASKD], rr[KCL];
    __shared__ float rsum;

    if (t < VDIM) {
        float s = 0.0f;
        for (int cc = 0; cc < NCLS; cc++) s += g_v[cc * VDIM + t];
        float m = s * (1.0f / 128.0f);
        float q = 0.0f;
        for (int cc = 0; cc < NCLS; cc++) {
            float d = g_v[cc * VDIM + t] - m;
            q += d * d;
        }
        vv[t]        = q * (1.0f / 127.0f);
        vv[VDIM + t] = m;
    }
    if (t == 0) {
        float ss = 0.0f;
        for (int i = 0; i < NCLS; i++) ss += g_simpart[i];
        vv[64] = 1.0f;
        vv[65] = ss;
    }
    __syncthreads();

    float a = b2[t];
    for (int i = 0; i < 66; i++) a += vv[i] * W2[i * TASKD + t];
    task[t] = fmaxf(a, 0.0f);
    __syncthreads();

    if (t < KCL) {
        float d2 = 0.0f;
        for (int j = 0; j < TASKD; j++) {
            float df = task[j] - memv[t * TASKD + j];
            d2 += df * df;
        }
        rr[t] = 1.0f / (sqrtf(d2) + 1.0f);
    }
    __syncthreads();
    if (t == 0) {
        float s = 0.0f;
        for (int k = 0; k < KCL; k++) s += rr[k];
        rsum = s;
    }
    __syncthreads();

    float o = 0.0f;
    for (int k = 0; k < KCL; k++) o += rr[k] * memv[k * TASKD + t];
    out[t] = o / rsum;
}

// ---------------------------------------------------------------------------
extern "C" void kernel_launch(void* const* d_in, const int* in_sizes, int n_in,
                              void* d_out, int out_size)
{
    (void)in_sizes; (void)n_in; (void)out_size;
    const float* x   = (const float*)d_in[0];
    const float* W0  = (const float*)d_in[2];
    const float* b0  = (const float*)d_in[3];
    const float* W1  = (const float*)d_in[4];
    const float* b1  = (const float*)d_in[5];
    const float* Ws  = (const float*)d_in[6];
    const float* bs  = (const float*)d_in[7];
    const float* Wv0 = (const float*)d_in[8];
    const float* bv0 = (const float*)d_in[9];
    const float* Wv1 = (const float*)d_in[10];
    const float* bv1 = (const float*)d_in[11];
    const float* W2  = (const float*)d_in[12];
    const float* b2  = (const float*)d_in[13];
    const float* mem = (const float*)d_in[14];
    float* out = (float*)d_out;

    const int smem_bytes = 3 * STAGE;  // 48 KB
    cudaFuncSetAttribute(gemm_kernel<0>, cudaFuncAttributeMaxDynamicSharedMemorySize, smem_bytes);
    cudaFuncSetAttribute(gemm_kernel<1>, cudaFuncAttributeMaxDynamicSharedMemorySize, smem_bytes);

    splitx_kernel<<<NROWS * (EDIM / 4) / 256, 256>>>(x);
    splitw_kernel<<<dim3(1024, 2), 256>>>(W0, W1);
    gemm_kernel<0><<<dim3(4, NMT), 256, smem_bytes>>>(b0);
    gemm_kernel<1><<<dim3(4, NMT), 256, smem_bytes>>>(b1);
    k2a_kernel<<<NCLS, 64>>>(Ws, bs, Wv0, bv0, Wv1, bv1);
    k2b_kernel<<<NCLS, 256>>>();
    k3_kernel<<<1, 64>>>(W2, b2, mem, out);
}

// round 12
// speedup vs baseline: 2.1185x; 2.1185x over previous
#include <cuda_runtime.h>
#include <cuda_fp16.h>

#define NCLS 128
#define EDIM 512
#define SHOT 1024
#define NROWS (NCLS * SHOT)
#define EMBD 64
#define VDIM 32
#define TASKD 64
#define KCL 32

#define NMT (NROWS / 128)    // 1024 M-tiles of 128 rows (class-major: 8 tiles/class)
#define TK 64                // 64 fp16 per k-chunk -> 128B rows, SW128 swizzle
#define NK (EDIM / TK)       // 8 k-chunks
#define STAGE 32768          // A 16K | B 16K

typedef unsigned int u32;
typedef unsigned long long u64;

// ------------------------- device scratch ----------------------------------
__device__ __align__(128) __half g_X [(size_t)NROWS * EDIM];   // fp16(x), class-major
__device__ __align__(128) __half g_H [(size_t)NROWS * EDIM];   // fp16(relu(xW0+b0))
__device__ __align__(128) __half g_W [2 * EDIM * EDIM];        // [mat][n][k] fp16
__device__ float g_psum[NMT * EDIM];
__device__ float g_psq [NMT * EDIM];
__device__ float g_mnorm[NCLS * EDIM];
__device__ float g_v[NCLS * VDIM];
__device__ float g_simpart[NCLS];

// ------------------------- helpers -----------------------------------------
__device__ __forceinline__ u32 smem_u32(const void* p) {
    u32 a;
    asm("{ .reg .u64 t; cvta.to.shared.u64 t, %1; cvt.u32.u64 %0, t; }" : "=r"(a) : "l"(p));
    return a;
}
__device__ __forceinline__ void cpa16(u32 dst, const void* src) {
    asm volatile("cp.async.cg.shared.global [%0], [%1], 16;" :: "r"(dst), "l"(src) : "memory");
}
#define CP_COMMIT() asm volatile("cp.async.commit_group;" ::: "memory")
#define CP_WAIT(n)  asm volatile("cp.async.wait_group %0;" :: "n"(n) : "memory")

__device__ __forceinline__ u32 swz128(u32 off) { return off ^ ((off >> 3) & 0x70); }

__device__ __forceinline__ void ldm4(u32* r, u32 addr) {
    asm volatile("ldmatrix.sync.aligned.m8n8.x4.shared.b16 {%0,%1,%2,%3}, [%4];"
                 : "=r"(r[0]), "=r"(r[1]), "=r"(r[2]), "=r"(r[3]) : "r"(addr));
}
__device__ __forceinline__ void mma16816(float* d, const u32* a, const u32* b) {
    asm volatile(
        "mma.sync.aligned.m16n8k16.row.col.f32.f16.f16.f32 "
        "{%0,%1,%2,%3}, {%4,%5,%6,%7}, {%8,%9}, {%0,%1,%2,%3};"
        : "+f"(d[0]), "+f"(d[1]), "+f"(d[2]), "+f"(d[3])
        : "r"(a[0]), "r"(a[1]), "r"(a[2]), "r"(a[3]), "r"(b[0]), "r"(b[1]));
}
__device__ __forceinline__ u32 hpair(float a, float b) {
    __half2 t = __floats2half2_rn(a, b);
    return *reinterpret_cast<u32*>(&t);
}

// ---------------------------------------------------------------------------
// splitx: x f32 [131072,512] row i=(shot*128+class) -> class-major fp16
// ---------------------------------------------------------------------------
__global__ __launch_bounds__(256) void splitx_kernel(const float* __restrict__ x)
{
    size_t g = (size_t)blockIdx.x * 256 + threadIdx.x;   // over NROWS*128 float4s
    int i = (int)(g >> 7), e4 = (int)(g & 127);
    float4 v = ((const float4*)(x + (size_t)i * EDIM))[e4];
    int p = (i & 127) * SHOT + (i >> 7);
    ((uint2*)(g_X + (size_t)p * EDIM))[e4] = make_uint2(hpair(v.x, v.y), hpair(v.z, v.w));
}

// ---------------------------------------------------------------------------
// splitw: W [512 k][512 n] f32 -> transposed [n][k] fp16
// ---------------------------------------------------------------------------
__global__ __launch_bounds__(256) void splitw_kernel(const float* __restrict__ W0,
                                                     const float* __restrict__ W1)
{
    int idx = blockIdx.x * 256 + threadIdx.x;            // 0..262143
    const float* W = blockIdx.y ? W1 : W0;
    size_t base = (size_t)blockIdx.y * EDIM * EDIM;
    int k = idx >> 9, n = idx & 511;
    g_W[base + (size_t)n * EDIM + k] = __float2half_rn(W[idx]);
}

// ---------------------------------------------------------------------------
// GEMM via mma.sync m16n8k16 fp16, single product (A_fp16 @ W_fp16, f32 acc).
// CTA tile 128(M) x 128(N), K chunks of 64 (128B rows, SW128), 3-stage
// cp.async pipeline (96KB) -> 2 CTAs/SM. 8 warps, warp grid 2(M) x 4(N),
// warp tile 64x32. Per stage: A 16KB | B 16KB.
// PHASE 0: H = relu(X@W0+b0) -> fp16 out
// PHASE 1: h = H@W1+b1 -> per-tile column sums of h, h^2
// ---------------------------------------------------------------------------
template <int PHASE>
__global__ __launch_bounds__(256, 2) void gemm_kernel(const float* __restrict__ bias)
{
    const int nh  = blockIdx.x;      // N tile (0..3)
    const int mt  = blockIdx.y;      // M tile (0..1023)
    const int tid = threadIdx.x;
    const int L   = tid & 31;
    const int warp = tid >> 5;
    const int warpM = warp & 1;      // 0..1
    const int warpN = warp >> 1;     // 0..3

    extern __shared__ __align__(1024) char sm[];
    const u32 smb = smem_u32(sm);

    const __half* A = (PHASE ? g_H : g_X);
    const __half* B = g_W + (size_t)PHASE * EDIM * EDIM;

    float c[4][4][4];
#pragma unroll
    for (int mf = 0; mf < 4; mf++)
#pragma unroll
        for (int nf = 0; nf < 4; nf++)
#pragma unroll
            for (int r = 0; r < 4; r++) c[mf][nf][r] = 0.0f;

    // ldmatrix lane address components (128B rows)
    const int rA0 = warpM * 64 + (L & 7) + 8 * ((L >> 3) & 1);
    const u32 kA  = (u32)(L >> 4) * 16;             // bytes within one k16 slab
    const int rB0 = warpN * 32 + (L & 7) + 8 * (L >> 4);
    const u32 kB  = (u32)((L >> 3) & 1) * 16;       // bytes

    auto load_stage = [&](int kc, int st) {
        const u32 base = smb + (u32)st * STAGE;
#pragma unroll
        for (int it = 0; it < 4; it++) {
            int t = tid + it * 256;          // 0..1023
            int row = t >> 3, seg = t & 7;
            u32 off = swz128((u32)(row * 128 + seg * 16));
            cpa16(base + off,         A + (size_t)(mt * 128 + row) * EDIM + kc * TK + seg * 8);
            cpa16(base + 16384 + off, B + (size_t)(nh * 128 + row) * EDIM + kc * TK + seg * 8);
        }
        CP_COMMIT();
    };

    load_stage(0, 0);
    load_stage(1, 1);
    int st = 0;
    for (int kc = 0; kc < NK; kc++) {
        if (kc < NK - 2)      { load_stage(kc + 2, (st + 2) % 3); CP_WAIT(2); }
        else if (kc == NK - 2) CP_WAIT(1);
        else                   CP_WAIT(0);
        __syncthreads();

        const u32 base = smb + (u32)st * STAGE;
        const u32 aB = base, bB = base + 16384;
#pragma unroll
        for (int kk = 0; kk < 4; kk++) {     // four k16 steps per 64-chunk
            u32 bfr[2][4];
#pragma unroll
            for (int nf2 = 0; nf2 < 2; nf2++) {
                u32 off = swz128((u32)((rB0 + nf2 * 16) * 128) + (u32)(kk * 32) + kB);
                ldm4(bfr[nf2], bB + off);
            }
#pragma unroll
            for (int mf = 0; mf < 4; mf++) {
                u32 a[4];
                u32 off = swz128((u32)((rA0 + mf * 16) * 128) + (u32)(kk * 32) + kA);
                ldm4(a, aB + off);
#pragma unroll
                for (int nf = 0; nf < 4; nf++)
                    mma16816(c[mf][nf], a, &bfr[nf >> 1][(nf & 1) * 2]);
            }
        }
        __syncthreads();
        st = (st + 1) % 3;
    }

    // ------------------------------ epilogue -------------------------------
    const int colT = nh * 128 + warpN * 32 + 2 * (L & 3);   // global col of par 0
    float bv[4][2];
#pragma unroll
    for (int nf = 0; nf < 4; nf++) {
        bv[nf][0] = bias[colT + nf * 8];
        bv[nf][1] = bias[colT + nf * 8 + 1];
    }

    if (PHASE == 0) {
#pragma unroll
        for (int mf = 0; mf < 4; mf++) {
            const int r0 = mt * 128 + warpM * 64 + mf * 16 + (L >> 2);
            const int r1 = r0 + 8;
#pragma unroll
            for (int nf = 0; nf < 4; nf++) {
                const int col = colT + nf * 8;
                float h0 = fmaxf(c[mf][nf][0] + bv[nf][0], 0.0f);
                float h1 = fmaxf(c[mf][nf][1] + bv[nf][1], 0.0f);
                float h2 = fmaxf(c[mf][nf][2] + bv[nf][0], 0.0f);
                float h3 = fmaxf(c[mf][nf][3] + bv[nf][1], 0.0f);
                *(u32*)(g_H + (size_t)r0 * EDIM + col) = hpair(h0, h1);
                *(u32*)(g_H + (size_t)r1 * EDIM + col) = hpair(h2, h3);
            }
        }
    } else {
        float s[4][2], q[4][2];
#pragma unroll
        for (int nf = 0; nf < 4; nf++)
#pragma unroll
            for (int par = 0; par < 2; par++) { s[nf][par] = 0.0f; q[nf][par] = 0.0f; }
#pragma unroll
        for (int mf = 0; mf < 4; mf++)
#pragma unroll
            for (int nf = 0; nf < 4; nf++) {
                float h0 = c[mf][nf][0] + bv[nf][0];
                float h1 = c[mf][nf][1] + bv[nf][1];
                float h2 = c[mf][nf][2] + bv[nf][0];
                float h3 = c[mf][nf][3] + bv[nf][1];
                s[nf][0] += h0 + h2; q[nf][0] += h0 * h0 + h2 * h2;
                s[nf][1] += h1 + h3; q[nf][1] += h1 * h1 + h3 * h3;
            }
#pragma unroll
        for (int m = 4; m <= 16; m <<= 1)
#pragma unroll
            for (int nf = 0; nf < 4; nf++)
#pragma unroll
                for (int par = 0; par < 2; par++) {
                    s[nf][par] += __shfl_xor_sync(0xFFFFFFFFu, s[nf][par], m);
                    q[nf][par] += __shfl_xor_sync(0xFFFFFFFFu, q[nf][par], m);
                }
        float* reds = (float*)sm;          // [2][128]
        float* redq = reds + 256;
        if (L < 4) {
#pragma unroll
            for (int nf = 0; nf < 4; nf++)
#pragma unroll
                for (int par = 0; par < 2; par++) {
                    int col = warpN * 32 + nf * 8 + 2 * L + par;
                    reds[warpM * 128 + col] = s[nf][par];
                    redq[warpM * 128 + col] = q[nf][par];
                }
        }
        __syncthreads();
        if (tid < 128) {
            g_psum[(size_t)mt * EDIM + nh * 128 + tid] = reds[tid] + reds[128 + tid];
            g_psq [(size_t)mt * EDIM + nh * 128 + tid] = redq[tid] + redq[128 + tid];
        }
    }
}

// ---------------------------------------------------------------------------
// k2a: per class — reduce 8 tile partials, mean/var, mnorm, stats MLP -> v
// ---------------------------------------------------------------------------
__global__ __launch_bounds__(64)
void k2a_kernel(const float* __restrict__ Ws,  const float* __restrict__ bs,
                const float* __restrict__ Wv0, const float* __restrict__ bv0,
                const float* __restrict__ Wv1, const float* __restrict__ bv1)
{
    const int c = blockIdx.x;
    const int t = threadIdx.x;
    __shared__ float mean_s[EDIM], var_s[EDIM], red[64], sv[EMBD], u[VDIM];

    for (int e = t; e < EDIM; e += 64) {
        float ss = 0.0f, sq = 0.0f;
#pragma unroll
        for (int sub = 0; sub < 8; sub++) {
            ss += g_psum[(size_t)(c * 8 + sub) * EDIM + e];
            sq += g_psq [(size_t)(c * 8 + sub) * EDIM + e];
        }
        float m = ss * (1.0f / 1024.0f);
        mean_s[e] = m;
        var_s[e]  = (sq - 1024.0f * m * m) * (1.0f / 1023.0f);
    }
    __syncthreads();

    float ps = 0.0f;
    for (int e = t; e < EDIM; e += 64) { float m = mean_s[e]; ps += m * m; }
    red[t] = ps; __syncthreads();
    for (int off = 32; off > 0; off >>= 1) {
        if (t < off) red[t] += red[t + off];
        __syncthreads();
    }
    float inv = 1.0f / fmaxf(sqrtf(red[0]), 1e-7f);
    for (int e = t; e < EDIM; e += 64) g_mnorm[c * EDIM + e] = mean_s[e] * inv;

    float acc = bs[t] + Ws[1024 * EMBD + t];   // Nc == 1
    for (int i = 0; i < EDIM; i++) acc += var_s[i] * Ws[i * EMBD + t];
    for (int i = 0; i < EDIM; i++) acc += mean_s[i] * Ws[(EDIM + i) * EMBD + t];
    sv[t] = fmaxf(acc, 0.0f);
    __syncthreads();

    if (t < VDIM) {
        float a = bv0[t];
        for (int i = 0; i < EMBD; i++) a += sv[i] * Wv0[i * VDIM + t];
        u[t] = fmaxf(a, 0.0f);
    }
    __syncthreads();
    if (t < VDIM) {
        float a = bv1[t];
        for (int i = 0; i < VDIM; i++) a += u[i] * Wv1[i * VDIM + t];
        g_v[c * VDIM + t] = a;
    }
}

// ---------------------------------------------------------------------------
__global__ __launch_bounds__(256) void k2b_kernel()
{
    const int i = blockIdx.x;
    const int t = threadIdx.x;
    __shared__ float mi[EDIM];
    __shared__ float red[256];
    for (int e = t; e < EDIM; e += 256) mi[e] = g_mnorm[i * EDIM + e];
    __syncthreads();
    float acc = 0.0f;
    for (int e = t; e < EDIM; e += 256) {
        float ws = 0.0f;
        for (int j = i + 1; j < NCLS; j++) ws += (float)(j - i) * g_mnorm[j * EDIM + e];
        acc += ws * mi[e];
    }
    red[t] = acc; __syncthreads();
    for (int off = 128; off > 0; off >>= 1) {
        if (t < off) red[t] += red[t + off];
        __syncthreads();
    }
    if (t == 0) g_simpart[i] = red[0];
}

// ---------------------------------------------------------------------------
__global__ __launch_bounds__(64)
void k3_kernel(const float* __restrict__ W2, const float* __restrict__ b2,
               const float* __restrict__ memv, float* __restrict__ out)
{
    const int t = threadIdx.x;
    __shared__ float vv[66], task[TASKD], rr[KCL];
    __shared__ float rsum;

    if (t < VDIM) {
        float s = 0.0f;
        for (int cc = 0; cc < NCLS; cc++) s += g_v[cc * VDIM + t];
        float m = s * (1.0f / 128.0f);
        float q = 0.0f;
        for (int cc = 0; cc < NCLS; cc++) {
            float d = g_v[cc * VDIM + t] - m;
            q += d * d;
        }
        vv[t]        = q * (1.0f / 127.0f);
        vv[VDIM + t] = m;
    }
    if (t == 0) {
        float ss = 0.0f;
        for (int i = 0; i < NCLS; i++) ss += g_simpart[i];
        vv[64] = 1.0f;
        vv[65] = ss;
    }
    __syncthreads();

    float a = b2[t];
    for (int i = 0; i < 66; i++) a += vv[i] * W2[i * TASKD + t];
    task[t] = fmaxf(a, 0.0f);
    __syncthreads();

    if (t < KCL) {
        float d2 = 0.0f;
        for (int j = 0; j < TASKD; j++) {
            float df = task[j] - memv[t * TASKD + j];
            d2 += df * df;
        }
        rr[t] = 1.0f / (sqrtf(d2) + 1.0f);
    }
    __syncthreads();
    if (t == 0) {
        float s = 0.0f;
        for (int k = 0; k < KCL; k++) s += rr[k];
        rsum = s;
    }
    __syncthreads();

    float o = 0.0f;
    for (int k = 0; k < KCL; k++) o += rr[k] * memv[k * TASKD + t];
    out[t] = o / rsum;
}

// ---------------------------------------------------------------------------
extern "C" void kernel_launch(void* const* d_in, const int* in_sizes, int n_in,
                              void* d_out, int out_size)
{
    (void)in_sizes; (void)n_in; (void)out_size;
    const float* x   = (const float*)d_in[0];
    const float* W0  = (const float*)d_in[2];
    const float* b0  = (const float*)d_in[3];
    const float* W1  = (const float*)d_in[4];
    const float* b1  = (const float*)d_in[5];
    const float* Ws  = (const float*)d_in[6];
    const float* bs  = (const float*)d_in[7];
    const float* Wv0 = (const float*)d_in[8];
    const float* bv0 = (const float*)d_in[9];
    const float* Wv1 = (const float*)d_in[10];
    const float* bv1 = (const float*)d_in[11];
    const float* W2  = (const float*)d_in[12];
    const float* b2  = (const float*)d_in[13];
    const float* mem = (const float*)d_in[14];
    float* out = (float*)d_out;

    const int smem_bytes = 3 * STAGE;  // 96 KB
    cudaFuncSetAttribute(gemm_kernel<0>, cudaFuncAttributeMaxDynamicSharedMemorySize, smem_bytes);
    cudaFuncSetAttribute(gemm_kernel<1>, cudaFuncAttributeMaxDynamicSharedMemorySize, smem_bytes);

    splitx_kernel<<<NROWS * (EDIM / 4) / 256, 256>>>(x);
    splitw_kernel<<<dim3(1024, 2), 256>>>(W0, W1);
    gemm_kernel<0><<<dim3(4, NMT), 256, smem_bytes>>>(b0);
    gemm_kernel<1><<<dim3(4, NMT), 256, smem_bytes>>>(b1);
    k2a_kernel<<<NCLS, 64>>>(Ws, bs, Wv0, bv0, Wv1, bv1);
    k2b_kernel<<<NCLS, 256>>>();
    k3_kernel<<<1, 64>>>(W2, b2, mem, out);
}

// round 13
// speedup vs baseline: 2.1542x; 1.0169x over previous
#include <cuda_runtime.h>
#include <cuda_fp16.h>

#define NCLS 128
#define EDIM 512
#define SHOT 1024
#define NROWS (NCLS * SHOT)
#define EMBD 64
#define VDIM 32
#define TASKD 64
#define KCL 32

#define NMT (NROWS / 128)    // 1024 M-tiles of 128 rows (class-major: 8 tiles/class)
#define TK 32
#define NK (EDIM / TK)       // 16 k-chunks
#define STAGE 16384          // A 8K | B 8K

typedef unsigned int u32;
typedef unsigned long long u64;

// ------------------------- device scratch ----------------------------------
__device__ __align__(128) __half g_X [(size_t)NROWS * EDIM];   // fp16(x), class-major
__device__ __align__(128) __half g_H [(size_t)NROWS * EDIM];   // fp16(relu(xW0+b0))
__device__ __align__(128) __half g_W [2 * EDIM * EDIM];        // [mat][n][k] fp16
__device__ float g_psum[NMT * EDIM];
__device__ float g_psq [NMT * EDIM];
__device__ float g_mnorm[NCLS * EDIM];
__device__ float g_v[NCLS * VDIM];
__device__ float g_simpart[NCLS];

// ------------------------- helpers -----------------------------------------
__device__ __forceinline__ u32 smem_u32(const void* p) {
    u32 a;
    asm("{ .reg .u64 t; cvta.to.shared.u64 t, %1; cvt.u32.u64 %0, t; }" : "=r"(a) : "l"(p));
    return a;
}
__device__ __forceinline__ void cpa16(u32 dst, const void* src) {
    asm volatile("cp.async.cg.shared.global [%0], [%1], 16;" :: "r"(dst), "l"(src) : "memory");
}
#define CP_COMMIT() asm volatile("cp.async.commit_group;" ::: "memory")
#define CP_WAIT(n)  asm volatile("cp.async.wait_group %0;" :: "n"(n) : "memory")

__device__ __forceinline__ u32 swz64(u32 off) { return off ^ ((off >> 3) & 0x30); }

__device__ __forceinline__ void ldm4(u32* r, u32 addr) {
    asm volatile("ldmatrix.sync.aligned.m8n8.x4.shared.b16 {%0,%1,%2,%3}, [%4];"
                 : "=r"(r[0]), "=r"(r[1]), "=r"(r[2]), "=r"(r[3]) : "r"(addr));
}
__device__ __forceinline__ void mma16816(float* d, const u32* a, const u32* b) {
    asm volatile(
        "mma.sync.aligned.m16n8k16.row.col.f32.f16.f16.f32 "
        "{%0,%1,%2,%3}, {%4,%5,%6,%7}, {%8,%9}, {%0,%1,%2,%3};"
        : "+f"(d[0]), "+f"(d[1]), "+f"(d[2]), "+f"(d[3])
        : "r"(a[0]), "r"(a[1]), "r"(a[2]), "r"(a[3]), "r"(b[0]), "r"(b[1]));
}
__device__ __forceinline__ u32 hpair(float a, float b) {
    __half2 t = __floats2half2_rn(a, b);
    return *reinterpret_cast<u32*>(&t);
}

// ---------------------------------------------------------------------------
// splitx: x f32 [131072,512] row i=(shot*128+class) -> class-major fp16
// ---------------------------------------------------------------------------
__global__ __launch_bounds__(256) void splitx_kernel(const float* __restrict__ x)
{
    size_t g = (size_t)blockIdx.x * 256 + threadIdx.x;   // over NROWS*128 float4s
    int i = (int)(g >> 7), e4 = (int)(g & 127);
    float4 v = ((const float4*)(x + (size_t)i * EDIM))[e4];
    int p = (i & 127) * SHOT + (i >> 7);
    ((uint2*)(g_X + (size_t)p * EDIM))[e4] = make_uint2(hpair(v.x, v.y), hpair(v.z, v.w));
}

// ---------------------------------------------------------------------------
// splitw: W [512 k][512 n] f32 -> transposed [n][k] fp16
// ---------------------------------------------------------------------------
__global__ __launch_bounds__(256) void splitw_kernel(const float* __restrict__ W0,
                                                     const float* __restrict__ W1)
{
    int idx = blockIdx.x * 256 + threadIdx.x;            // 0..262143
    const float* W = blockIdx.y ? W1 : W0;
    size_t base = (size_t)blockIdx.y * EDIM * EDIM;
    int k = idx >> 9, n = idx & 511;
    g_W[base + (size_t)n * EDIM + k] = __float2half_rn(W[idx]);
}

// ---------------------------------------------------------------------------
// GEMM via mma.sync m16n8k16 fp16, single product (A_fp16 @ W_fp16, f32 acc).
// CTA tile 128(M) x 128(N), K chunks of 32, 4-stage cp.async pipeline (64KB)
// -> 2 CTAs/SM. 8 warps, warp grid 2(M) x 4(N), warp tile 64x32.
// Per stage: A 8KB | B 8KB, 64B rows, SW64 swizzle. Prefetch distance 3;
// steady-state CP_WAIT(3) drains exactly the stage being consumed.
// PHASE 0: H = relu(X@W0+b0) -> fp16 out
// PHASE 1: h = H@W1+b1 -> per-tile column sums of h, h^2
// ---------------------------------------------------------------------------
template <int PHASE>
__global__ __launch_bounds__(256, 2) void gemm_kernel(const float* __restrict__ bias)
{
    const int nh  = blockIdx.x;      // N tile (0..3)
    const int mt  = blockIdx.y;      // M tile (0..1023)
    const int tid = threadIdx.x;
    const int L   = tid & 31;
    const int warp = tid >> 5;
    const int warpM = warp & 1;      // 0..1
    const int warpN = warp >> 1;     // 0..3

    extern __shared__ __align__(1024) char sm[];
    const u32 smb = smem_u32(sm);

    const __half* A = (PHASE ? g_H : g_X);
    const __half* B = g_W + (size_t)PHASE * EDIM * EDIM;

    float c[4][4][4];
#pragma unroll
    for (int mf = 0; mf < 4; mf++)
#pragma unroll
        for (int nf = 0; nf < 4; nf++)
#pragma unroll
            for (int r = 0; r < 4; r++) c[mf][nf][r] = 0.0f;

    // ldmatrix lane address components (64B rows)
    const int rA0 = warpM * 64 + (L & 7) + 8 * ((L >> 3) & 1);
    const u32 kA  = (u32)(L >> 4) * 16;             // bytes within 32-elem chunk
    const int rB0 = warpN * 32 + (L & 7) + 8 * (L >> 4);
    const u32 kB  = (u32)((L >> 3) & 1) * 16;       // bytes

    auto load_stage = [&](int kc, int st) {
        const u32 base = smb + (u32)st * STAGE;
#pragma unroll
        for (int it = 0; it < 2; it++) {
            int t = tid + it * 256;          // 0..511
            int row = t >> 2, seg = t & 3;
            u32 off = swz64((u32)(row * 64 + seg * 16));
            cpa16(base + off,        A + (size_t)(mt * 128 + row) * EDIM + kc * TK + seg * 8);
            cpa16(base + 8192 + off, B + (size_t)(nh * 128 + row) * EDIM + kc * TK + seg * 8);
        }
        CP_COMMIT();
    };

    load_stage(0, 0);
    load_stage(1, 1);
    load_stage(2, 2);
    int st = 0;
    for (int kc = 0; kc < NK; kc++) {
        if (kc < NK - 3)       { load_stage(kc + 3, (st + 3) & 3); CP_WAIT(3); }
        else if (kc == NK - 3)   CP_WAIT(2);
        else if (kc == NK - 2)   CP_WAIT(1);
        else                     CP_WAIT(0);
        __syncthreads();

        const u32 base = smb + (u32)st * STAGE;
        const u32 aB = base, bB = base + 8192;
#pragma unroll
        for (int kk = 0; kk < 2; kk++) {
            u32 bfr[2][4];
#pragma unroll
            for (int nf2 = 0; nf2 < 2; nf2++) {
                u32 off = swz64((u32)((rB0 + nf2 * 16) * 64) + (u32)(kk * 32) + kB);
                ldm4(bfr[nf2], bB + off);
            }
#pragma unroll
            for (int mf = 0; mf < 4; mf++) {
                u32 a[4];
                u32 off = swz64((u32)((rA0 + mf * 16) * 64) + (u32)(kk * 32) + kA);
                ldm4(a, aB + off);
#pragma unroll
                for (int nf = 0; nf < 4; nf++)
                    mma16816(c[mf][nf], a, &bfr[nf >> 1][(nf & 1) * 2]);
            }
        }
        __syncthreads();
        st = (st + 1) & 3;
    }

    // ------------------------------ epilogue -------------------------------
    const int colT = nh * 128 + warpN * 32 + 2 * (L & 3);   // global col of par 0
    float bv[4][2];
#pragma unroll
    for (int nf = 0; nf < 4; nf++) {
        bv[nf][0] = bias[colT + nf * 8];
        bv[nf][1] = bias[colT + nf * 8 + 1];
    }

    if (PHASE == 0) {
#pragma unroll
        for (int mf = 0; mf < 4; mf++) {
            const int r0 = mt * 128 + warpM * 64 + mf * 16 + (L >> 2);
            const int r1 = r0 + 8;
#pragma unroll
            for (int nf = 0; nf < 4; nf++) {
                const int col = colT + nf * 8;
                float h0 = fmaxf(c[mf][nf][0] + bv[nf][0], 0.0f);
                float h1 = fmaxf(c[mf][nf][1] + bv[nf][1], 0.0f);
                float h2 = fmaxf(c[mf][nf][2] + bv[nf][0], 0.0f);
                float h3 = fmaxf(c[mf][nf][3] + bv[nf][1], 0.0f);
                *(u32*)(g_H + (size_t)r0 * EDIM + col) = hpair(h0, h1);
                *(u32*)(g_H + (size_t)r1 * EDIM + col) = hpair(h2, h3);
            }
        }
    } else {
        float s[4][2], q[4][2];
#pragma unroll
        for (int nf = 0; nf < 4; nf++)
#pragma unroll
            for (int par = 0; par < 2; par++) { s[nf][par] = 0.0f; q[nf][par] = 0.0f; }
#pragma unroll
        for (int mf = 0; mf < 4; mf++)
#pragma unroll
            for (int nf = 0; nf < 4; nf++) {
                float h0 = c[mf][nf][0] + bv[nf][0];
                float h1 = c[mf][nf][1] + bv[nf][1];
                float h2 = c[mf][nf][2] + bv[nf][0];
                float h3 = c[mf][nf][3] + bv[nf][1];
                s[nf][0] += h0 + h2; q[nf][0] += h0 * h0 + h2 * h2;
                s[nf][1] += h1 + h3; q[nf][1] += h1 * h1 + h3 * h3;
            }
#pragma unroll
        for (int m = 4; m <= 16; m <<= 1)
#pragma unroll
            for (int nf = 0; nf < 4; nf++)
#pragma unroll
                for (int par = 0; par < 2; par++) {
                    s[nf][par] += __shfl_xor_sync(0xFFFFFFFFu, s[nf][par], m);
                    q[nf][par] += __shfl_xor_sync(0xFFFFFFFFu, q[nf][par], m);
                }
        float* reds = (float*)sm;          // [2][128]
        float* redq = reds + 256;
        if (L < 4) {
#pragma unroll
            for (int nf = 0; nf < 4; nf++)
#pragma unroll
                for (int par = 0; par < 2; par++) {
                    int col = warpN * 32 + nf * 8 + 2 * L + par;
                    reds[warpM * 128 + col] = s[nf][par];
                    redq[warpM * 128 + col] = q[nf][par];
                }
        }
        __syncthreads();
        if (tid < 128) {
            g_psum[(size_t)mt * EDIM + nh * 128 + tid] = reds[tid] + reds[128 + tid];
            g_psq [(size_t)mt * EDIM + nh * 128 + tid] = redq[tid] + redq[128 + tid];
        }
    }
}

// ---------------------------------------------------------------------------
// k2a: per class — reduce 8 tile partials, mean/var, mnorm, stats MLP -> v
// 256 threads: 4 i-range groups x 64 output cols for the 1025-wide matvec.
// ---------------------------------------------------------------------------
__global__ __launch_bounds__(256)
void k2a_kernel(const float* __restrict__ Ws,  const float* __restrict__ bs,
                const float* __restrict__ Wv0, const float* __restrict__ bv0,
                const float* __restrict__ Wv1, const float* __restrict__ bv1)
{
    const int c = blockIdx.x;
    const int t = threadIdx.x;
    const int col = t & 63;
    const int qg  = t >> 6;     // 0..3
    __shared__ float mean_s[EDIM], var_s[EDIM], red[256], part[4][EMBD], sv[EMBD], u[VDIM];

    for (int e = t; e < EDIM; e += 256) {
        float ss = 0.0f, sq = 0.0f;
#pragma unroll
        for (int sub = 0; sub < 8; sub++) {
            ss += g_psum[(size_t)(c * 8 + sub) * EDIM + e];
            sq += g_psq [(size_t)(c * 8 + sub) * EDIM + e];
        }
        float m = ss * (1.0f / 1024.0f);
        mean_s[e] = m;
        var_s[e]  = (sq - 1024.0f * m * m) * (1.0f / 1023.0f);
    }
    __syncthreads();

    {
        float ps = 0.0f;
        for (int e = t; e < EDIM; e += 256) { float m = mean_s[e]; ps += m * m; }
        red[t] = ps;
    }
    __syncthreads();
    for (int off = 128; off > 0; off >>= 1) {
        if (t < off) red[t] += red[t + off];
        __syncthreads();
    }
    float inv = 1.0f / fmaxf(sqrtf(red[0]), 1e-7f);
    for (int e = t; e < EDIM; e += 256) g_mnorm[c * EDIM + e] = mean_s[e] * inv;

    // stats matvec: rows 0..511 = var, 512..1023 = mean, row 1024 = Nc(=1)
    {
        const float* src = (qg < 2) ? (var_s + qg * 256) : (mean_s + (qg - 2) * 256);
        const float* wp  = Ws + (size_t)(qg * 256) * EMBD + col;
        float acc = 0.0f;
        for (int ii = 0; ii < 256; ii++) acc += src[ii] * wp[(size_t)ii * EMBD];
        part[qg][col] = acc;
    }
    __syncthreads();
    if (t < EMBD) {
        float acc = part[0][t] + part[1][t] + part[2][t] + part[3][t]
                  + bs[t] + Ws[1024 * EMBD + t];
        sv[t] = fmaxf(acc, 0.0f);
    }
    __syncthreads();

    if (t < VDIM) {
        float a = bv0[t];
        for (int i = 0; i < EMBD; i++) a += sv[i] * Wv0[i * VDIM + t];
        u[t] = fmaxf(a, 0.0f);
    }
    __syncthreads();
    if (t < VDIM) {
        float a = bv1[t];
        for (int i = 0; i < VDIM; i++) a += u[i] * Wv1[i * VDIM + t];
        g_v[c * VDIM + t] = a;
    }
}

// ---------------------------------------------------------------------------
__global__ __launch_bounds__(256) void k2b_kernel()
{
    const int i = blockIdx.x;
    const int t = threadIdx.x;
    __shared__ float mi[EDIM];
    __shared__ float red[256];
    for (int e = t; e < EDIM; e += 256) mi[e] = g_mnorm[i * EDIM + e];
    __syncthreads();
    float acc = 0.0f;
    for (int e = t; e < EDIM; e += 256) {
        float ws = 0.0f;
        for (int j = i + 1; j < NCLS; j++) ws += (float)(j - i) * g_mnorm[j * EDIM + e];
        acc += ws * mi[e];
    }
    red[t] = acc; __syncthreads();
    for (int off = 128; off > 0; off >>= 1) {
        if (t < off) red[t] += red[t + off];
        __syncthreads();
    }
    if (t == 0) g_simpart[i] = red[0];
}

// ---------------------------------------------------------------------------
__global__ __launch_bounds__(64)
void k3_kernel(const float* __restrict__ W2, const float* __restrict__ b2,
               const float* __restrict__ memv, float* __restrict__ out)
{
    const int t = threadIdx.x;
    __shared__ float vv[66], task[TASKD], rr[KCL];
    __shared__ float rsum;

    if (t < VDIM) {
        float s = 0.0f;
        for (int cc = 0; cc < NCLS; cc++) s += g_v[cc * VDIM + t];
        float m = s * (1.0f / 128.0f);
        float q = 0.0f;
        for (int cc = 0; cc < NCLS; cc++) {
            float d = g_v[cc * VDIM + t] - m;
            q += d * d;
        }
        vv[t]        = q * (1.0f / 127.0f);
        vv[VDIM + t] = m;
    }
    if (t == 0) {
        float ss = 0.0f;
        for (int i = 0; i < NCLS; i++) ss += g_simpart[i];
        vv[64] = 1.0f;
        vv[65] = ss;
    }
    __syncthreads();

    float a = b2[t];
    for (int i = 0; i < 66; i++) a += vv[i] * W2[i * TASKD + t];
    task[t] = fmaxf(a, 0.0f);
    __syncthreads();

    if (t < KCL) {
        float d2 = 0.0f;
        for (int j = 0; j < TASKD; j++) {
            float df = task[j] - memv[t * TASKD + j];
            d2 += df * df;
        }
        rr[t] = 1.0f / (sqrtf(d2) + 1.0f);
    }
    __syncthreads();
    if (t == 0) {
        float s = 0.0f;
        for (int k = 0; k < KCL; k++) s += rr[k];
        rsum = s;
    }
    __syncthreads();

    float o = 0.0f;
    for (int k = 0; k < KCL; k++) o += rr[k] * memv[k * TASKD + t];
    out[t] = o / rsum;
}

// ---------------------------------------------------------------------------
extern "C" void kernel_launch(void* const* d_in, const int* in_sizes, int n_in,
                              void* d_out, int out_size)
{
    (void)in_sizes; (void)n_in; (void)out_size;
    const float* x   = (const float*)d_in[0];
    const float* W0  = (const float*)d_in[2];
    const float* b0  = (const float*)d_in[3];
    const float* W1  = (const float*)d_in[4];
    const float* b1  = (const float*)d_in[5];
    const float* Ws  = (const float*)d_in[6];
    const float* bs  = (const float*)d_in[7];
    const float* Wv0 = (const float*)d_in[8];
    const float* bv0 = (const float*)d_in[9];
    const float* Wv1 = (const float*)d_in[10];
    const float* bv1 = (const float*)d_in[11];
    const float* W2  = (const float*)d_in[12];
    const float* b2  = (const float*)d_in[13];
    const float* mem = (const float*)d_in[14];
    float* out = (float*)d_out;

    const int smem_bytes = 4 * STAGE;  // 64 KB
    cudaFuncSetAttribute(gemm_kernel<0>, cudaFuncAttributeMaxDynamicSharedMemorySize, smem_bytes);
    cudaFuncSetAttribute(gemm_kernel<1>, cudaFuncAttributeMaxDynamicSharedMemorySize, smem_bytes);

    splitx_kernel<<<NROWS * (EDIM / 4) / 256, 256>>>(x);
    splitw_kernel<<<dim3(1024, 2), 256>>>(W0, W1);
    gemm_kernel<0><<<dim3(4, NMT), 256, smem_bytes>>>(b0);
    gemm_kernel<1><<<dim3(4, NMT), 256, smem_bytes>>>(b1);
    k2a_kernel<<<NCLS, 256>>>(Ws, bs, Wv0, bv0, Wv1, bv1);
    k2b_kernel<<<NCLS, 256>>>();
    k3_kernel<<<1, 64>>>(W2, b2, mem, out);
}

// round 14
// speedup vs baseline: 2.3668x; 1.0987x over previous
#include <cuda_runtime.h>
#include <cuda_fp16.h>

#define NCLS 128
#define EDIM 512
#define SHOT 1024
#define NROWS (NCLS * SHOT)
#define EMBD 64
#define VDIM 32
#define TASKD 64
#define KCL 32

#define NMT (NROWS / 128)    // 1024 M-tiles of 128 rows (class-major: 8 tiles/class)
#define TK 32
#define NK (EDIM / TK)       // 16 k-chunks
#define STAGE 16384          // A 8K | B 8K

typedef unsigned int u32;
typedef unsigned long long u64;

// ------------------------- device scratch ----------------------------------
__device__ __align__(128) __half g_X [(size_t)NROWS * EDIM];   // fp16(x), class-major
__device__ __align__(128) __half g_H [(size_t)NROWS * EDIM];   // fp16(relu(xW0+b0))
__device__ __align__(128) __half g_W [2 * EDIM * EDIM];        // [mat][n][k] fp16
__device__ float g_psum[NMT * EDIM];
__device__ float g_psq [NMT * EDIM];
__device__ float g_mnorm[NCLS * EDIM];
__device__ float g_v[NCLS * VDIM];
__device__ float g_simpart[NCLS];

// ------------------------- helpers -----------------------------------------
__device__ __forceinline__ u32 smem_u32(const void* p) {
    u32 a;
    asm("{ .reg .u64 t; cvta.to.shared.u64 t, %1; cvt.u32.u64 %0, t; }" : "=r"(a) : "l"(p));
    return a;
}
__device__ __forceinline__ void cpa16(u32 dst, const void* src) {
    asm volatile("cp.async.cg.shared.global [%0], [%1], 16;" :: "r"(dst), "l"(src) : "memory");
}
#define CP_COMMIT() asm volatile("cp.async.commit_group;" ::: "memory")
#define CP_WAIT(n)  asm volatile("cp.async.wait_group %0;" :: "n"(n) : "memory")

__device__ __forceinline__ u32 swz64(u32 off) { return off ^ ((off >> 3) & 0x30); }

__device__ __forceinline__ void ldm4(u32* r, u32 addr) {
    asm volatile("ldmatrix.sync.aligned.m8n8.x4.shared.b16 {%0,%1,%2,%3}, [%4];"
                 : "=r"(r[0]), "=r"(r[1]), "=r"(r[2]), "=r"(r[3]) : "r"(addr));
}
__device__ __forceinline__ void mma16816(float* d, const u32* a, const u32* b) {
    asm volatile(
        "mma.sync.aligned.m16n8k16.row.col.f32.f16.f16.f32 "
        "{%0,%1,%2,%3}, {%4,%5,%6,%7}, {%8,%9}, {%0,%1,%2,%3};"
        : "+f"(d[0]), "+f"(d[1]), "+f"(d[2]), "+f"(d[3])
        : "r"(a[0]), "r"(a[1]), "r"(a[2]), "r"(a[3]), "r"(b[0]), "r"(b[1]));
}
__device__ __forceinline__ u32 hpair(float a, float b) {
    __half2 t = __floats2half2_rn(a, b);
    return *reinterpret_cast<u32*>(&t);
}

// ---------------------------------------------------------------------------
// splitx: x f32 [131072,512] row i=(shot*128+class) -> class-major fp16
// ---------------------------------------------------------------------------
__global__ __launch_bounds__(256) void splitx_kernel(const float* __restrict__ x)
{
    size_t g = (size_t)blockIdx.x * 256 + threadIdx.x;   // over NROWS*128 float4s
    int i = (int)(g >> 7), e4 = (int)(g & 127);
    float4 v = ((const float4*)(x + (size_t)i * EDIM))[e4];
    int p = (i & 127) * SHOT + (i >> 7);
    ((uint2*)(g_X + (size_t)p * EDIM))[e4] = make_uint2(hpair(v.x, v.y), hpair(v.z, v.w));
}

// ---------------------------------------------------------------------------
// splitw: W [512 k][512 n] f32 -> transposed [n][k] fp16
// ---------------------------------------------------------------------------
__global__ __launch_bounds__(256) void splitw_kernel(const float* __restrict__ W0,
                                                     const float* __restrict__ W1)
{
    int idx = blockIdx.x * 256 + threadIdx.x;            // 0..262143
    const float* W = blockIdx.y ? W1 : W0;
    size_t base = (size_t)blockIdx.y * EDIM * EDIM;
    int k = idx >> 9, n = idx & 511;
    g_W[base + (size_t)n * EDIM + k] = __float2half_rn(W[idx]);
}

// ---------------------------------------------------------------------------
// GEMM via mma.sync m16n8k16 fp16, single product (A_fp16 @ W_fp16, f32 acc).
// CTA tile 128(M) x 128(N), K chunks of 32, 3-stage cp.async pipeline (48KB)
// -> 2 CTAs/SM. 8 warps, warp grid 2(M) x 4(N), warp tile 64x32.
// Per stage: A 8KB | B 8KB, 64B rows, SW64 swizzle.  (Exact R9 config.)
// PHASE 0: H = relu(X@W0+b0) -> fp16 out
// PHASE 1: h = H@W1+b1 -> per-tile column sums of h, h^2
// ---------------------------------------------------------------------------
template <int PHASE>
__global__ __launch_bounds__(256, 2) void gemm_kernel(const float* __restrict__ bias)
{
    const int nh  = blockIdx.x;      // N tile (0..3)
    const int mt  = blockIdx.y;      // M tile (0..1023)
    const int tid = threadIdx.x;
    const int L   = tid & 31;
    const int warp = tid >> 5;
    const int warpM = warp & 1;      // 0..1
    const int warpN = warp >> 1;     // 0..3

    extern __shared__ __align__(1024) char sm[];
    const u32 smb = smem_u32(sm);

    const __half* A = (PHASE ? g_H : g_X);
    const __half* B = g_W + (size_t)PHASE * EDIM * EDIM;

    float c[4][4][4];
#pragma unroll
    for (int mf = 0; mf < 4; mf++)
#pragma unroll
        for (int nf = 0; nf < 4; nf++)
#pragma unroll
            for (int r = 0; r < 4; r++) c[mf][nf][r] = 0.0f;

    // ldmatrix lane address components (64B rows)
    const int rA0 = warpM * 64 + (L & 7) + 8 * ((L >> 3) & 1);
    const u32 kA  = (u32)(L >> 4) * 16;             // bytes within 32-elem chunk
    const int rB0 = warpN * 32 + (L & 7) + 8 * (L >> 4);
    const u32 kB  = (u32)((L >> 3) & 1) * 16;       // bytes

    auto load_stage = [&](int kc, int st) {
        const u32 base = smb + (u32)st * STAGE;
#pragma unroll
        for (int it = 0; it < 2; it++) {
            int t = tid + it * 256;          // 0..511
            int row = t >> 2, seg = t & 3;
            u32 off = swz64((u32)(row * 64 + seg * 16));
            cpa16(base + off,        A + (size_t)(mt * 128 + row) * EDIM + kc * TK + seg * 8);
            cpa16(base + 8192 + off, B + (size_t)(nh * 128 + row) * EDIM + kc * TK + seg * 8);
        }
        CP_COMMIT();
    };

    load_stage(0, 0);
    load_stage(1, 1);
    int st = 0;
    for (int kc = 0; kc < NK; kc++) {
        if (kc < NK - 2)      { load_stage(kc + 2, (st + 2) % 3); CP_WAIT(2); }
        else if (kc == NK - 2) CP_WAIT(1);
        else                   CP_WAIT(0);
        __syncthreads();

        const u32 base = smb + (u32)st * STAGE;
        const u32 aB = base, bB = base + 8192;
#pragma unroll
        for (int kk = 0; kk < 2; kk++) {
            u32 bfr[2][4];
#pragma unroll
            for (int nf2 = 0; nf2 < 2; nf2++) {
                u32 off = swz64((u32)((rB0 + nf2 * 16) * 64) + (u32)(kk * 32) + kB);
                ldm4(bfr[nf2], bB + off);
            }
#pragma unroll
            for (int mf = 0; mf < 4; mf++) {
                u32 a[4];
                u32 off = swz64((u32)((rA0 + mf * 16) * 64) + (u32)(kk * 32) + kA);
                ldm4(a, aB + off);
#pragma unroll
                for (int nf = 0; nf < 4; nf++)
                    mma16816(c[mf][nf], a, &bfr[nf >> 1][(nf & 1) * 2]);
            }
        }
        __syncthreads();
        st = (st + 1) % 3;
    }

    // ------------------------------ epilogue -------------------------------
    const int colT = nh * 128 + warpN * 32 + 2 * (L & 3);   // global col of par 0
    float bv[4][2];
#pragma unroll
    for (int nf = 0; nf < 4; nf++) {
        bv[nf][0] = bias[colT + nf * 8];
        bv[nf][1] = bias[colT + nf * 8 + 1];
    }

    if (PHASE == 0) {
#pragma unroll
        for (int mf = 0; mf < 4; mf++) {
            const int r0 = mt * 128 + warpM * 64 + mf * 16 + (L >> 2);
            const int r1 = r0 + 8;
#pragma unroll
            for (int nf = 0; nf < 4; nf++) {
                const int col = colT + nf * 8;
                float h0 = fmaxf(c[mf][nf][0] + bv[nf][0], 0.0f);
                float h1 = fmaxf(c[mf][nf][1] + bv[nf][1], 0.0f);
                float h2 = fmaxf(c[mf][nf][2] + bv[nf][0], 0.0f);
                float h3 = fmaxf(c[mf][nf][3] + bv[nf][1], 0.0f);
                *(u32*)(g_H + (size_t)r0 * EDIM + col) = hpair(h0, h1);
                *(u32*)(g_H + (size_t)r1 * EDIM + col) = hpair(h2, h3);
            }
        }
    } else {
        float s[4][2], q[4][2];
#pragma unroll
        for (int nf = 0; nf < 4; nf++)
#pragma unroll
            for (int par = 0; par < 2; par++) { s[nf][par] = 0.0f; q[nf][par] = 0.0f; }
#pragma unroll
        for (int mf = 0; mf < 4; mf++)
#pragma unroll
            for (int nf = 0; nf < 4; nf++) {
                float h0 = c[mf][nf][0] + bv[nf][0];
                float h1 = c[mf][nf][1] + bv[nf][1];
                float h2 = c[mf][nf][2] + bv[nf][0];
                float h3 = c[mf][nf][3] + bv[nf][1];
                s[nf][0] += h0 + h2; q[nf][0] += h0 * h0 + h2 * h2;
                s[nf][1] += h1 + h3; q[nf][1] += h1 * h1 + h3 * h3;
            }
#pragma unroll
        for (int m = 4; m <= 16; m <<= 1)
#pragma unroll
            for (int nf = 0; nf < 4; nf++)
#pragma unroll
                for (int par = 0; par < 2; par++) {
                    s[nf][par] += __shfl_xor_sync(0xFFFFFFFFu, s[nf][par], m);
                    q[nf][par] += __shfl_xor_sync(0xFFFFFFFFu, q[nf][par], m);
                }
        float* reds = (float*)sm;          // [2][128]
        float* redq = reds + 256;
        if (L < 4) {
#pragma unroll
            for (int nf = 0; nf < 4; nf++)
#pragma unroll
                for (int par = 0; par < 2; par++) {
                    int col = warpN * 32 + nf * 8 + 2 * L + par;
                    reds[warpM * 128 + col] = s[nf][par];
                    redq[warpM * 128 + col] = q[nf][par];
                }
        }
        __syncthreads();
        if (tid < 128) {
            g_psum[(size_t)mt * EDIM + nh * 128 + tid] = reds[tid] + reds[128 + tid];
            g_psq [(size_t)mt * EDIM + nh * 128 + tid] = redq[tid] + redq[128 + tid];
        }
    }
}

// ---------------------------------------------------------------------------
// k2a: per class — reduce 8 tile partials, mean/var, mnorm, stats MLP -> v
// 256 threads: 4 i-range groups x 64 output cols for the 1025-wide matvec.
// ---------------------------------------------------------------------------
__global__ __launch_bounds__(256)
void k2a_kernel(const float* __restrict__ Ws,  const float* __restrict__ bs,
                const float* __restrict__ Wv0, const float* __restrict__ bv0,
                const float* __restrict__ Wv1, const float* __restrict__ bv1)
{
    const int c = blockIdx.x;
    const int t = threadIdx.x;
    const int col = t & 63;
    const int qg  = t >> 6;     // 0..3
    __shared__ float mean_s[EDIM], var_s[EDIM], red[256], part[4][EMBD], sv[EMBD], u[VDIM];

    for (int e = t; e < EDIM; e += 256) {
        float ss = 0.0f, sq = 0.0f;
#pragma unroll
        for (int sub = 0; sub < 8; sub++) {
            ss += g_psum[(size_t)(c * 8 + sub) * EDIM + e];
            sq += g_psq [(size_t)(c * 8 + sub) * EDIM + e];
        }
        float m = ss * (1.0f / 1024.0f);
        mean_s[e] = m;
        var_s[e]  = (sq - 1024.0f * m * m) * (1.0f / 1023.0f);
    }
    __syncthreads();

    {
        float ps = 0.0f;
        for (int e = t; e < EDIM; e += 256) { float m = mean_s[e]; ps += m * m; }
        red[t] = ps;
    }
    __syncthreads();
    for (int off = 128; off > 0; off >>= 1) {
        if (t < off) red[t] += red[t + off];
        __syncthreads();
    }
    float inv = 1.0f / fmaxf(sqrtf(red[0]), 1e-7f);
    for (int e = t; e < EDIM; e += 256) g_mnorm[c * EDIM + e] = mean_s[e] * inv;

    // stats matvec: rows 0..511 = var, 512..1023 = mean, row 1024 = Nc(=1)
    {
        const float* src = (qg < 2) ? (var_s + qg * 256) : (mean_s + (qg - 2) * 256);
        const float* wp  = Ws + (size_t)(qg * 256) * EMBD + col;
        float acc = 0.0f;
        for (int ii = 0; ii < 256; ii++) acc += src[ii] * wp[(size_t)ii * EMBD];
        part[qg][col] = acc;
    }
    __syncthreads();
    if (t < EMBD) {
        float acc = part[0][t] + part[1][t] + part[2][t] + part[3][t]
                  + bs[t] + Ws[1024 * EMBD + t];
        sv[t] = fmaxf(acc, 0.0f);
    }
    __syncthreads();

    if (t < VDIM) {
        float a = bv0[t];
        for (int i = 0; i < EMBD; i++) a += sv[i] * Wv0[i * VDIM + t];
        u[t] = fmaxf(a, 0.0f);
    }
    __syncthreads();
    if (t < VDIM) {
        float a = bv1[t];
        for (int i = 0; i < VDIM; i++) a += u[i] * Wv1[i * VDIM + t];
        g_v[c * VDIM + t] = a;
    }
}

// ---------------------------------------------------------------------------
__global__ __launch_bounds__(256) void k2b_kernel()
{
    const int i = blockIdx.x;
    const int t = threadIdx.x;
    __shared__ float mi[EDIM];
    __shared__ float red[256];
    for (int e = t; e < EDIM; e += 256) mi[e] = g_mnorm[i * EDIM + e];
    __syncthreads();
    float acc = 0.0f;
    for (int e = t; e < EDIM; e += 256) {
        float ws = 0.0f;
        for (int j = i + 1; j < NCLS; j++) ws += (float)(j - i) * g_mnorm[j * EDIM + e];
        acc += ws * mi[e];
    }
    red[t] = acc; __syncthreads();
    for (int off = 128; off > 0; off >>= 1) {
        if (t < off) red[t] += red[t + off];
        __syncthreads();
    }
    if (t == 0) g_simpart[i] = red[0];
}

// ---------------------------------------------------------------------------
__global__ __launch_bounds__(64)
void k3_kernel(const float* __restrict__ W2, const float* __restrict__ b2,
               const float* __restrict__ memv, float* __restrict__ out)
{
    const int t = threadIdx.x;
    __shared__ float vv[66], task[TASKD], rr[KCL];
    __shared__ float rsum;

    if (t < VDIM) {
        float s = 0.0f;
        for (int cc = 0; cc < NCLS; cc++) s += g_v[cc * VDIM + t];
        float m = s * (1.0f / 128.0f);
        float q = 0.0f;
        for (int cc = 0; cc < NCLS; cc++) {
            float d = g_v[cc * VDIM + t] - m;
            q += d * d;
        }
        vv[t]        = q * (1.0f / 127.0f);
        vv[VDIM + t] = m;
    }
    if (t == 0) {
        float ss = 0.0f;
        for (int i = 0; i < NCLS; i++) ss += g_simpart[i];
        vv[64] = 1.0f;
        vv[65] = ss;
    }
    __syncthreads();

    float a = b2[t];
    for (int i = 0; i < 66; i++) a += vv[i] * W2[i * TASKD + t];
    task[t] = fmaxf(a, 0.0f);
    __syncthreads();

    if (t < KCL) {
        float d2 = 0.0f;
        for (int j = 0; j < TASKD; j++) {
            float df = task[j] - memv[t * TASKD + j];
            d2 += df * df;
        }
        rr[t] = 1.0f / (sqrtf(d2) + 1.0f);
    }
    __syncthreads();
    if (t == 0) {
        float s = 0.0f;
        for (int k = 0; k < KCL; k++) s += rr[k];
        rsum = s;
    }
    __syncthreads();

    float o = 0.0f;
    for (int k = 0; k < KCL; k++) o += rr[k] * memv[k * TASKD + t];
    out[t] = o / rsum;
}

// ---------------------------------------------------------------------------
extern "C" void kernel_launch(void* const* d_in, const int* in_sizes, int n_in,
                              void* d_out, int out_size)
{
    (void)in_sizes; (void)n_in; (void)out_size;
    const float* x   = (const float*)d_in[0];
    const float* W0  = (const float*)d_in[2];
    const float* b0  = (const float*)d_in[3];
    const float* W1  = (const float*)d_in[4];
    const float* b1  = (const float*)d_in[5];
    const float* Ws  = (const float*)d_in[6];
    const float* bs  = (const float*)d_in[7];
    const float* Wv0 = (const float*)d_in[8];
    const float* bv0 = (const float*)d_in[9];
    const float* Wv1 = (const float*)d_in[10];
    const float* bv1 = (const float*)d_in[11];
    const float* W2  = (const float*)d_in[12];
    const float* b2  = (const float*)d_in[13];
    const float* mem = (const float*)d_in[14];
    float* out = (float*)d_out;

    const int smem_bytes = 3 * STAGE;  // 48 KB
    cudaFuncSetAttribute(gemm_kernel<0>, cudaFuncAttributeMaxDynamicSharedMemorySize, smem_bytes);
    cudaFuncSetAttribute(gemm_kernel<1>, cudaFuncAttributeMaxDynamicSharedMemorySize, smem_bytes);

    splitx_kernel<<<NROWS * (EDIM / 4) / 256, 256>>>(x);
    splitw_kernel<<<dim3(1024, 2), 256>>>(W0, W1);
    gemm_kernel<0><<<dim3(4, NMT), 256, smem_bytes>>>(b0);
    gemm_kernel<1><<<dim3(4, NMT), 256, smem_bytes>>>(b1);
    k2a_kernel<<<NCLS, 256>>>(Ws, bs, Wv0, bv0, Wv1, bv1);
    k2b_kernel<<<NCLS, 256>>>();
    k3_kernel<<<1, 64>>>(W2, b2, mem, out);
}

// round 15
// speedup vs baseline: 2.3695x; 1.0012x over previous
#include <cuda_runtime.h>
#include <cuda_fp16.h>

#define NCLS 128
#define EDIM 512
#define SHOT 1024
#define NROWS (NCLS * SHOT)
#define EMBD 64
#define VDIM 32
#define TASKD 64
#define KCL 32

#define NMT (NROWS / 128)    // 1024 M-tiles of 128 rows (class-major: 8 tiles/class)
#define TK 32
#define NK (EDIM / TK)       // 16 k-chunks
#define STAGE 16384          // A 8K | B 8K

typedef unsigned int u32;
typedef unsigned long long u64;

// ------------------------- device scratch ----------------------------------
__device__ __align__(128) __half g_X [(size_t)NROWS * EDIM];   // fp16(x), class-major
__device__ __align__(128) __half g_H [(size_t)NROWS * EDIM];   // fp16(relu(xW0+b0))
__device__ __align__(128) __half g_W [2 * EDIM * EDIM];        // [mat][n][k] fp16
__device__ float g_psum[NMT * EDIM];
__device__ float g_psq [NMT * EDIM];
__device__ float g_mnorm[NCLS * EDIM];
__device__ float g_v[NCLS * VDIM];
__device__ float g_simsum;

// ------------------------- helpers -----------------------------------------
__device__ __forceinline__ u32 smem_u32(const void* p) {
    u32 a;
    asm("{ .reg .u64 t; cvta.to.shared.u64 t, %1; cvt.u32.u64 %0, t; }" : "=r"(a) : "l"(p));
    return a;
}
__device__ __forceinline__ void cpa16(u32 dst, const void* src) {
    asm volatile("cp.async.cg.shared.global [%0], [%1], 16;" :: "r"(dst), "l"(src) : "memory");
}
#define CP_COMMIT() asm volatile("cp.async.commit_group;" ::: "memory")
#define CP_WAIT(n)  asm volatile("cp.async.wait_group %0;" :: "n"(n) : "memory")

__device__ __forceinline__ u32 swz64(u32 off) { return off ^ ((off >> 3) & 0x30); }

__device__ __forceinline__ void ldm4(u32* r, u32 addr) {
    asm volatile("ldmatrix.sync.aligned.m8n8.x4.shared.b16 {%0,%1,%2,%3}, [%4];"
                 : "=r"(r[0]), "=r"(r[1]), "=r"(r[2]), "=r"(r[3]) : "r"(addr));
}
__device__ __forceinline__ void mma16816(float* d, const u32* a, const u32* b) {
    asm volatile(
        "mma.sync.aligned.m16n8k16.row.col.f32.f16.f16.f32 "
        "{%0,%1,%2,%3}, {%4,%5,%6,%7}, {%8,%9}, {%0,%1,%2,%3};"
        : "+f"(d[0]), "+f"(d[1]), "+f"(d[2]), "+f"(d[3])
        : "r"(a[0]), "r"(a[1]), "r"(a[2]), "r"(a[3]), "r"(b[0]), "r"(b[1]));
}
__device__ __forceinline__ u32 hpair(float a, float b) {
    __half2 t = __floats2half2_rn(a, b);
    return *reinterpret_cast<u32*>(&t);
}

// ---------------------------------------------------------------------------
// splitx: x f32 [131072,512] row i=(shot*128+class) -> class-major fp16
// ---------------------------------------------------------------------------
__global__ __launch_bounds__(256) void splitx_kernel(const float* __restrict__ x)
{
    size_t g = (size_t)blockIdx.x * 256 + threadIdx.x;   // over NROWS*128 float4s
    int i = (int)(g >> 7), e4 = (int)(g & 127);
    float4 v = ((const float4*)(x + (size_t)i * EDIM))[e4];
    int p = (i & 127) * SHOT + (i >> 7);
    ((uint2*)(g_X + (size_t)p * EDIM))[e4] = make_uint2(hpair(v.x, v.y), hpair(v.z, v.w));
}

// ---------------------------------------------------------------------------
// splitw: W [512 k][512 n] f32 -> transposed [n][k] fp16
// ---------------------------------------------------------------------------
__global__ __launch_bounds__(256) void splitw_kernel(const float* __restrict__ W0,
                                                     const float* __restrict__ W1)
{
    int idx = blockIdx.x * 256 + threadIdx.x;            // 0..262143
    const float* W = blockIdx.y ? W1 : W0;
    size_t base = (size_t)blockIdx.y * EDIM * EDIM;
    int k = idx >> 9, n = idx & 511;
    g_W[base + (size_t)n * EDIM + k] = __float2half_rn(W[idx]);
}

// ---------------------------------------------------------------------------
// GEMM via mma.sync m16n8k16 fp16, single product (A_fp16 @ W_fp16, f32 acc).
// CTA tile 128(M) x 128(N), K chunks of 32, 3-stage cp.async pipeline (48KB)
// -> 2 CTAs/SM. 8 warps, warp grid 2(M) x 4(N), warp tile 64x32.
// Per stage: A 8KB | B 8KB, 64B rows, SW64 swizzle.  (FROZEN R9/R13 config.)
// PHASE 0: H = relu(X@W0+b0) -> fp16 out
// PHASE 1: h = H@W1+b1 -> per-tile column sums of h, h^2
// ---------------------------------------------------------------------------
template <int PHASE>
__global__ __launch_bounds__(256, 2) void gemm_kernel(const float* __restrict__ bias)
{
    const int nh  = blockIdx.x;      // N tile (0..3)
    const int mt  = blockIdx.y;      // M tile (0..1023)
    const int tid = threadIdx.x;
    const int L   = tid & 31;
    const int warp = tid >> 5;
    const int warpM = warp & 1;      // 0..1
    const int warpN = warp >> 1;     // 0..3

    extern __shared__ __align__(1024) char sm[];
    const u32 smb = smem_u32(sm);

    const __half* A = (PHASE ? g_H : g_X);
    const __half* B = g_W + (size_t)PHASE * EDIM * EDIM;

    float c[4][4][4];
#pragma unroll
    for (int mf = 0; mf < 4; mf++)
#pragma unroll
        for (int nf = 0; nf < 4; nf++)
#pragma unroll
            for (int r = 0; r < 4; r++) c[mf][nf][r] = 0.0f;

    // ldmatrix lane address components (64B rows)
    const int rA0 = warpM * 64 + (L & 7) + 8 * ((L >> 3) & 1);
    const u32 kA  = (u32)(L >> 4) * 16;             // bytes within 32-elem chunk
    const int rB0 = warpN * 32 + (L & 7) + 8 * (L >> 4);
    const u32 kB  = (u32)((L >> 3) & 1) * 16;       // bytes

    auto load_stage = [&](int kc, int st) {
        const u32 base = smb + (u32)st * STAGE;
#pragma unroll
        for (int it = 0; it < 2; it++) {
            int t = tid + it * 256;          // 0..511
            int row = t >> 2, seg = t & 3;
            u32 off = swz64((u32)(row * 64 + seg * 16));
            cpa16(base + off,        A + (size_t)(mt * 128 + row) * EDIM + kc * TK + seg * 8);
            cpa16(base + 8192 + off, B + (size_t)(nh * 128 + row) * EDIM + kc * TK + seg * 8);
        }
        CP_COMMIT();
    };

    load_stage(0, 0);
    load_stage(1, 1);
    int st = 0;
    for (int kc = 0; kc < NK; kc++) {
        if (kc < NK - 2)      { load_stage(kc + 2, (st + 2) % 3); CP_WAIT(2); }
        else if (kc == NK - 2) CP_WAIT(1);
        else                   CP_WAIT(0);
        __syncthreads();

        const u32 base = smb + (u32)st * STAGE;
        const u32 aB = base, bB = base + 8192;
#pragma unroll
        for (int kk = 0; kk < 2; kk++) {
            u32 bfr[2][4];
#pragma unroll
            for (int nf2 = 0; nf2 < 2; nf2++) {
                u32 off = swz64((u32)((rB0 + nf2 * 16) * 64) + (u32)(kk * 32) + kB);
                ldm4(bfr[nf2], bB + off);
            }
#pragma unroll
            for (int mf = 0; mf < 4; mf++) {
                u32 a[4];
                u32 off = swz64((u32)((rA0 + mf * 16) * 64) + (u32)(kk * 32) + kA);
                ldm4(a, aB + off);
#pragma unroll
                for (int nf = 0; nf < 4; nf++)
                    mma16816(c[mf][nf], a, &bfr[nf >> 1][(nf & 1) * 2]);
            }
        }
        __syncthreads();
        st = (st + 1) % 3;
    }

    // ------------------------------ epilogue -------------------------------
    const int colT = nh * 128 + warpN * 32 + 2 * (L & 3);   // global col of par 0
    float bv[4][2];
#pragma unroll
    for (int nf = 0; nf < 4; nf++) {
        bv[nf][0] = bias[colT + nf * 8];
        bv[nf][1] = bias[colT + nf * 8 + 1];
    }

    if (PHASE == 0) {
#pragma unroll
        for (int mf = 0; mf < 4; mf++) {
            const int r0 = mt * 128 + warpM * 64 + mf * 16 + (L >> 2);
            const int r1 = r0 + 8;
#pragma unroll
            for (int nf = 0; nf < 4; nf++) {
                const int col = colT + nf * 8;
                float h0 = fmaxf(c[mf][nf][0] + bv[nf][0], 0.0f);
                float h1 = fmaxf(c[mf][nf][1] + bv[nf][1], 0.0f);
                float h2 = fmaxf(c[mf][nf][2] + bv[nf][0], 0.0f);
                float h3 = fmaxf(c[mf][nf][3] + bv[nf][1], 0.0f);
                *(u32*)(g_H + (size_t)r0 * EDIM + col) = hpair(h0, h1);
                *(u32*)(g_H + (size_t)r1 * EDIM + col) = hpair(h2, h3);
            }
        }
    } else {
        float s[4][2], q[4][2];
#pragma unroll
        for (int nf = 0; nf < 4; nf++)
#pragma unroll
            for (int par = 0; par < 2; par++) { s[nf][par] = 0.0f; q[nf][par] = 0.0f; }
#pragma unroll
        for (int mf = 0; mf < 4; mf++)
#pragma unroll
            for (int nf = 0; nf < 4; nf++) {
                float h0 = c[mf][nf][0] + bv[nf][0];
                float h1 = c[mf][nf][1] + bv[nf][1];
                float h2 = c[mf][nf][2] + bv[nf][0];
                float h3 = c[mf][nf][3] + bv[nf][1];
                s[nf][0] += h0 + h2; q[nf][0] += h0 * h0 + h2 * h2;
                s[nf][1] += h1 + h3; q[nf][1] += h1 * h1 + h3 * h3;
            }
#pragma unroll
        for (int m = 4; m <= 16; m <<= 1)
#pragma unroll
            for (int nf = 0; nf < 4; nf++)
#pragma unroll
                for (int par = 0; par < 2; par++) {
                    s[nf][par] += __shfl_xor_sync(0xFFFFFFFFu, s[nf][par], m);
                    q[nf][par] += __shfl_xor_sync(0xFFFFFFFFu, q[nf][par], m);
                }
        float* reds = (float*)sm;          // [2][128]
        float* redq = reds + 256;
        if (L < 4) {
#pragma unroll
            for (int nf = 0; nf < 4; nf++)
#pragma unroll
                for (int par = 0; par < 2; par++) {
                    int col = warpN * 32 + nf * 8 + 2 * L + par;
                    reds[warpM * 128 + col] = s[nf][par];
                    redq[warpM * 128 + col] = q[nf][par];
                }
        }
        __syncthreads();
        if (tid < 128) {
            g_psum[(size_t)mt * EDIM + nh * 128 + tid] = reds[tid] + reds[128 + tid];
            g_psq [(size_t)mt * EDIM + nh * 128 + tid] = redq[tid] + redq[128 + tid];
        }
    }
}

// ---------------------------------------------------------------------------
// k2a: per class — reduce 8 tile partials, mean/var, mnorm, stats MLP -> v
// 256 threads: 4 i-range groups x 64 output cols for the 1025-wide matvec.
// ---------------------------------------------------------------------------
__global__ __launch_bounds__(256)
void k2a_kernel(const float* __restrict__ Ws,  const float* __restrict__ bs,
                const float* __restrict__ Wv0, const float* __restrict__ bv0,
                const float* __restrict__ Wv1, const float* __restrict__ bv1)
{
    const int c = blockIdx.x;
    const int t = threadIdx.x;
    const int col = t & 63;
    const int qg  = t >> 6;     // 0..3
    __shared__ float mean_s[EDIM], var_s[EDIM], red[256], part[4][EMBD], sv[EMBD], u[VDIM];

    for (int e = t; e < EDIM; e += 256) {
        float ss = 0.0f, sq = 0.0f;
#pragma unroll
        for (int sub = 0; sub < 8; sub++) {
            ss += g_psum[(size_t)(c * 8 + sub) * EDIM + e];
            sq += g_psq [(size_t)(c * 8 + sub) * EDIM + e];
        }
        float m = ss * (1.0f / 1024.0f);
        mean_s[e] = m;
        var_s[e]  = (sq - 1024.0f * m * m) * (1.0f / 1023.0f);
    }
    __syncthreads();

    {
        float ps = 0.0f;
        for (int e = t; e < EDIM; e += 256) { float m = mean_s[e]; ps += m * m; }
        red[t] = ps;
    }
    __syncthreads();
    for (int off = 128; off > 0; off >>= 1) {
        if (t < off) red[t] += red[t + off];
        __syncthreads();
    }
    float inv = 1.0f / fmaxf(sqrtf(red[0]), 1e-7f);
    for (int e = t; e < EDIM; e += 256) g_mnorm[c * EDIM + e] = mean_s[e] * inv;

    // stats matvec: rows 0..511 = var, 512..1023 = mean, row 1024 = Nc(=1)
    {
        const float* src = (qg < 2) ? (var_s + qg * 256) : (mean_s + (qg - 2) * 256);
        const float* wp  = Ws + (size_t)(qg * 256) * EMBD + col;
        float acc = 0.0f;
        for (int ii = 0; ii < 256; ii++) acc += src[ii] * wp[(size_t)ii * EMBD];
        part[qg][col] = acc;
    }
    __syncthreads();
    if (t < EMBD) {
        float acc = part[0][t] + part[1][t] + part[2][t] + part[3][t]
                  + bs[t] + Ws[1024 * EMBD + t];
        sv[t] = fmaxf(acc, 0.0f);
    }
    __syncthreads();

    if (t < VDIM) {
        float a = bv0[t];
        for (int i = 0; i < EMBD; i++) a += sv[i] * Wv0[i * VDIM + t];
        u[t] = fmaxf(a, 0.0f);
    }
    __syncthreads();
    if (t < VDIM) {
        float a = bv1[t];
        for (int i = 0; i < VDIM; i++) a += u[i] * Wv1[i * VDIM + t];
        g_v[c * VDIM + t] = a;
    }
}

// ---------------------------------------------------------------------------
// k2b: single block, 512 threads (thread = column e). Suffix scan over i:
//   sim_sum = sum_e sum_i m_i[e] * (Ssuf - i*Tsuf),
//   Ssuf = sum_{j>i} j*m_j[e], Tsuf = sum_{j>i} m_j[e].
// Emits the scalar g_simsum directly.
// ---------------------------------------------------------------------------
__global__ __launch_bounds__(512) void k2b_kernel()
{
    const int e = threadIdx.x;     // 0..511
    __shared__ float red[512];
    float Ssuf = 0.0f, Tsuf = 0.0f, acc = 0.0f;
    for (int i = NCLS - 1; i >= 0; i--) {
        float m = g_mnorm[i * EDIM + e];
        float fi = (float)i;
        acc  += m * (Ssuf - fi * Tsuf);
        Ssuf += fi * m;
        Tsuf += m;
    }
    red[e] = acc; __syncthreads();
    for (int off = 256; off > 0; off >>= 1) {
        if (e < off) red[e] += red[e + off];
        __syncthreads();
    }
    if (e == 0) g_simsum = red[0];
}

// ---------------------------------------------------------------------------
// k3: final — 256 threads, parallel class loops.
// v stats (two-pass var), task MLP, distances, soft-assign, out.
// ---------------------------------------------------------------------------
__global__ __launch_bounds__(256)
void k3_kernel(const float* __restrict__ W2, const float* __restrict__ b2,
               const float* __restrict__ memv, float* __restrict__ out)
{
    const int t = threadIdx.x;
    __shared__ float part8[8][VDIM];      // class-group partials
    __shared__ float marr[VDIM];
    __shared__ float vv[66], tp[4][TASKD], task[TASKD], rr[KCL];
    __shared__ float rsum;

    const int vd  = t & 31;    // v-dim
    const int cg  = t >> 5;    // class group 0..7

    // pass 1: mean
    {
        float s = 0.0f;
        for (int cc = cg; cc < NCLS; cc += 8) s += g_v[cc * VDIM + vd];
        part8[cg][vd] = s;
    }
    __syncthreads();
    if (t < VDIM) {
        float s = 0.0f;
#pragma unroll
        for (int g = 0; g < 8; g++) s += part8[g][t];
        float m = s * (1.0f / 128.0f);
        marr[t] = m;
        vv[VDIM + t] = m;
    }
    __syncthreads();
    // pass 2: two-pass variance
    {
        float m = marr[vd];
        float q = 0.0f;
        for (int cc = cg; cc < NCLS; cc += 8) {
            float d = g_v[cc * VDIM + vd] - m;
            q += d * d;
        }
        part8[cg][vd] = q;
    }
    __syncthreads();
    if (t < VDIM) {
        float q = 0.0f;
#pragma unroll
        for (int g = 0; g < 8; g++) q += part8[g][t];
        vv[t] = q * (1.0f / 127.0f);
    }
    if (t == 0) {
        vv[64] = 1.0f;          // v_N (Nc == 1 for every class)
        vv[65] = g_simsum;      // sim_sum
    }
    __syncthreads();

    // task matvec: 66 rows split over 4 groups x 64 cols
    {
        const int col = t & 63, qg = t >> 6;
        float acc = 0.0f;
        for (int i = qg; i < 66; i += 4) acc += vv[i] * W2[i * TASKD + col];
        tp[qg][col] = acc;
    }
    __syncthreads();
    if (t < TASKD)
        task[t] = fmaxf(tp[0][t] + tp[1][t] + tp[2][t] + tp[3][t] + b2[t], 0.0f);
    __syncthreads();

    // distances: 32 clusters x 8 lanes each (8 dims per lane, shfl reduce)
    {
        const int k = t >> 3, piece = t & 7;
        float d2 = 0.0f;
#pragma unroll
        for (int j = 0; j < 8; j++) {
            int jj = piece * 8 + j;
            float df = task[jj] - memv[k * TASKD + jj];
            d2 += df * df;
        }
        d2 += __shfl_xor_sync(0xFFFFFFFFu, d2, 1);
        d2 += __shfl_xor_sync(0xFFFFFFFFu, d2, 2);
        d2 += __shfl_xor_sync(0xFFFFFFFFu, d2, 4);
        if (piece == 0) rr[k] = 1.0f / (sqrtf(d2) + 1.0f);   // TEMP=1
    }
    __syncthreads();
    if (t == 0) {
        float s = 0.0f;
        for (int k = 0; k < KCL; k++) s += rr[k];
        rsum = s;
    }
    __syncthreads();

    if (t < TASKD) {
        float o = 0.0f;
        for (int k = 0; k < KCL; k++) o += rr[k] * memv[k * TASKD + t];
        out[t] = o / rsum;
    }
}

// ---------------------------------------------------------------------------
extern "C" void kernel_launch(void* const* d_in, const int* in_sizes, int n_in,
                              void* d_out, int out_size)
{
    (void)in_sizes; (void)n_in; (void)out_size;
    const float* x   = (const float*)d_in[0];
    const float* W0  = (const float*)d_in[2];
    const float* b0  = (const float*)d_in[3];
    const float* W1  = (const float*)d_in[4];
    const float* b1  = (const float*)d_in[5];
    const float* Ws  = (const float*)d_in[6];
    const float* bs  = (const float*)d_in[7];
    const float* Wv0 = (const float*)d_in[8];
    const float* bv0 = (const float*)d_in[9];
    const float* Wv1 = (const float*)d_in[10];
    const float* bv1 = (const float*)d_in[11];
    const float* W2  = (const float*)d_in[12];
    const float* b2  = (const float*)d_in[13];
    const float* mem = (const float*)d_in[14];
    float* out = (float*)d_out;

    const int smem_bytes = 3 * STAGE;  // 48 KB
    cudaFuncSetAttribute(gemm_kernel<0>, cudaFuncAttributeMaxDynamicSharedMemorySize, smem_bytes);
    cudaFuncSetAttribute(gemm_kernel<1>, cudaFuncAttributeMaxDynamicSharedMemorySize, smem_bytes);

    splitx_kernel<<<NROWS * (EDIM / 4) / 256, 256>>>(x);
    splitw_kernel<<<dim3(1024, 2), 256>>>(W0, W1);
    gemm_kernel<0><<<dim3(4, NMT), 256, smem_bytes>>>(b0);
    gemm_kernel<1><<<dim3(4, NMT), 256, smem_bytes>>>(b1);
    k2a_kernel<<<NCLS, 256>>>(Ws, bs, Wv0, bv0, Wv1, bv1);
    k2b_kernel<<<1, 512>>>();
    k3_kernel<<<1, 256>>>(W2, b2, mem, out);
}